// round 4
// baseline (speedup 1.0000x reference)
#include <cuda_runtime.h>
#include <math.h>

// Shapes (fixed by dataset):
//   features: [B=2, C=512, H=50, W=64] float32
//   roiss   : [B=2, N=128, 4]          float32
//   out     : [B, N, C]                float32
#define BB 2
#define CC 512
#define HH 50
#define WW 64
#define NN 128
#define HWSZ (HH * WW)   // 3200

// Scratch: features transposed to [B, H, W, C]  (13.1 MB)
__device__ float g_tfeat[BB * HWSZ * CC];

// ---------------------------------------------------------------------------
// Kernel 1: transpose [B, C, HW] -> [B, HW, C], 32x32 smem tiles, coalesced
// both sides. Fires PDL trigger when done so the pool can begin launching.
// ---------------------------------------------------------------------------
__global__ __launch_bounds__(256) void transpose_kernel(
    const float* __restrict__ feat)
{
    __shared__ float tile[32][33];

    const int b   = blockIdx.z;
    const int c0  = blockIdx.y * 32;
    const int hw0 = blockIdx.x * 32;
    const int tx  = threadIdx.x;       // 0..31
    const int ty  = threadIdx.y;       // 0..7

    const float* src = feat + (size_t)b * CC * HWSZ;
    float* dst       = g_tfeat + (size_t)b * HWSZ * CC;

    #pragma unroll
    for (int j = 0; j < 32; j += 8)
        tile[ty + j][tx] = src[(size_t)(c0 + ty + j) * HWSZ + (hw0 + tx)];
    __syncthreads();

    #pragma unroll
    for (int j = 0; j < 32; j += 8)
        dst[(size_t)(hw0 + ty + j) * CC + (c0 + tx)] = tile[tx][ty + j];

    // PDL: allow dependent (pool) grid to launch; its griddepcontrol.wait
    // guarantees visibility of the stores above.
    asm volatile("griddepcontrol.launch_dependents;");
}

// ---------------------------------------------------------------------------
// Kernel 2: ROI max-pool from [B, H, W, C].
//   grid  = (B*N, 2), block = 512 = 64 float4-lanes x 8 row-groups.
// Row-group g handles exactly window row y1+g (height <= 7 -> one load wave
// of <= 8 independent LDG.128 per thread). Partials combine via smem tree.
// Box is computed once per block (thread 0), overlapped with the PDL wait.
// ---------------------------------------------------------------------------
struct Box { int x1, xe, y1, ye; };

__global__ __launch_bounds__(512) void pool_kernel(
    const float* __restrict__ rois,
    float* __restrict__ out)
{
    const int bn = blockIdx.x;                 // 0 .. B*N-1
    const int b  = bn / NN;
    const int c4 = threadIdx.x & 63;           // float4 channel lane
    const int g  = threadIdx.x >> 6;           // window row group (0..7)
    const int c  = blockIdx.y * 256 + c4 * 4;  // first channel of this lane

    __shared__ Box sbox;
    __shared__ float4 part[8][64];

    if (threadIdx.x == 0) {
        // --- box computation (byte-identical to jax reference path) ---
        const float4 r = reinterpret_cast<const float4*>(rois)[bn];
        const float nx1 = __fmul_rn(__fdiv_rn(r.x, 1024.0f), (float)WW);
        const float ny1 = __fmul_rn(__fdiv_rn(r.y,  800.0f), (float)HH);
        const float nx2 = __fmul_rn(__fdiv_rn(r.z, 1024.0f), (float)WW);
        const float ny2 = __fmul_rn(__fdiv_rn(r.w,  800.0f), (float)HH);

        int x1 = max((int)floorf(nx1), 0);
        int y1 = max((int)floorf(ny1), 0);
        int x2 = max((int)ceilf(nx2), 0);
        int y2 = max((int)ceilf(ny2), 0);

        if (x1 == 0 && x2 == 0) x2 = 1;
        if (y1 == 0 && y2 == 0) y2 = 1;
        if (x1 >= WW) x1 = WW - 1;
        if (y1 >= HH) y1 = HH - 1;

        sbox.x1 = x1;
        sbox.xe = min(x2, WW);
        sbox.y1 = y1;
        sbox.ye = min(y2, HH);
    }

    // PDL: wait for the transpose grid's stores to be visible.
    asm volatile("griddepcontrol.wait;");
    __syncthreads();

    const int x1 = sbox.x1, xe = sbox.xe, y1 = sbox.y1, ye = sbox.ye;

    const float* base = g_tfeat + (size_t)b * HWSZ * CC + c;

    float4 m = make_float4(-INFINITY, -INFINITY, -INFINITY, -INFINITY);

    // This group's row(s): y1+g (+8 stride safety; height <= 7 here).
    for (int y = y1 + g; y < ye; y += 8) {
        const float* row = base + (size_t)(y * WW) * CC;
        // window width <= 7; 8 predicated LDG.128, all independent.
        #pragma unroll
        for (int i = 0; i < 8; ++i) {
            const int x = x1 + i;
            if (x < xe) {
                const float4 v =
                    *reinterpret_cast<const float4*>(row + (size_t)x * CC);
                m.x = fmaxf(m.x, v.x);
                m.y = fmaxf(m.y, v.y);
                m.z = fmaxf(m.z, v.z);
                m.w = fmaxf(m.w, v.w);
            }
        }
        for (int x = x1 + 8; x < xe; ++x) {    // safety, never taken here
            const float4 v =
                *reinterpret_cast<const float4*>(row + (size_t)x * CC);
            m.x = fmaxf(m.x, v.x);
            m.y = fmaxf(m.y, v.y);
            m.z = fmaxf(m.z, v.z);
            m.w = fmaxf(m.w, v.w);
        }
    }

    part[g][c4] = m;
    __syncthreads();

    // Tree combine: 8 -> 4 -> write
    if (g < 4) {
        float4 a = part[g][c4];
        const float4 o = part[g + 4][c4];
        a.x = fmaxf(a.x, o.x);
        a.y = fmaxf(a.y, o.y);
        a.z = fmaxf(a.z, o.z);
        a.w = fmaxf(a.w, o.w);
        part[g][c4] = a;
    }
    __syncthreads();

    if (g == 0) {
        float4 a = part[0][c4];
        const float4 b1 = part[1][c4];
        const float4 b2 = part[2][c4];
        const float4 b3 = part[3][c4];
        a.x = fmaxf(fmaxf(a.x, b1.x), fmaxf(b2.x, b3.x));
        a.y = fmaxf(fmaxf(a.y, b1.y), fmaxf(b2.y, b3.y));
        a.z = fmaxf(fmaxf(a.z, b1.z), fmaxf(b2.z, b3.z));
        a.w = fmaxf(fmaxf(a.w, b1.w), fmaxf(b2.w, b3.w));
        *reinterpret_cast<float4*>(out + (size_t)bn * CC + c) = a;
    }
}

extern "C" void kernel_launch(void* const* d_in, const int* in_sizes, int n_in,
                              void* d_out, int out_size)
{
    const float* feat = (const float*)d_in[0];   // [B, C, H, W]
    const float* rois = (const float*)d_in[1];   // [B, N, 4]
    float* out        = (float*)d_out;           // [B, N, C]
    (void)in_sizes; (void)n_in; (void)out_size;

    dim3 tgrid(HWSZ / 32, CC / 32, BB);          // 100 x 16 x 2
    dim3 tblock(32, 8);
    transpose_kernel<<<tgrid, tblock>>>(feat);

    // Pool launched with PDL so its prologue (box math) overlaps the
    // transpose epilogue; data dependency enforced by griddepcontrol.wait.
    cudaLaunchConfig_t cfg = {};
    cfg.gridDim  = dim3(BB * NN, 2);             // 256 x 2
    cfg.blockDim = dim3(512);
    cudaLaunchAttribute attrs[1];
    attrs[0].id = cudaLaunchAttributeProgrammaticStreamSerialization;
    attrs[0].val.programmaticStreamSerializationAllowed = 1;
    cfg.attrs    = attrs;
    cfg.numAttrs = 1;
    cudaLaunchKernelEx(&cfg, pool_kernel, rois, out);
}

// round 5
// speedup vs baseline: 1.1696x; 1.1696x over previous
#include <cuda_runtime.h>
#include <math.h>

// Shapes (fixed by dataset):
//   features: [B=2, C=512, H=50, W=64] float32
//   roiss   : [B=2, N=128, 4]          float32
//   out     : [B, N, C]                float32
#define BB 2
#define CC 512
#define HH 50
#define WW 64
#define NN 128
#define HWSZ (HH * WW)   // 3200

// ---------------------------------------------------------------------------
// Single fused kernel, original [B, C, H, W] layout.
//   grid  = (B*N, 16)  — blockIdx.x = roi, blockIdx.y = 32-channel tile
//   block = 256        — 8 warps; each warp: 4 channels x 8 window columns
// Lane l -> channel c0 + l/8, window column x1 + l%8. Window rows (<=7)
// are 8 predicated unrolled loads (MLP=8). Column-max via shfl_xor within
// the 8-lane group; lanes l%8==0 write 4 consecutive channels (coalesced).
// ---------------------------------------------------------------------------
__global__ __launch_bounds__(256) void roipool_fused_kernel(
    const float* __restrict__ feat,
    const float* __restrict__ rois,
    float* __restrict__ out)
{
    const int bn   = blockIdx.x;            // 0 .. B*N-1
    const int b    = bn / NN;
    const int w    = threadIdx.x >> 5;      // warp 0..7
    const int lane = threadIdx.x & 31;
    const int csub = lane >> 3;             // 0..3
    const int xoff = lane & 7;              // 0..7
    const int c    = blockIdx.y * 32 + w * 4 + csub;

    // --- box computation (byte-identical to jax reference path) ---
    const float4 r = reinterpret_cast<const float4*>(rois)[bn];
    const float nx1 = __fmul_rn(__fdiv_rn(r.x, 1024.0f), (float)WW);
    const float ny1 = __fmul_rn(__fdiv_rn(r.y,  800.0f), (float)HH);
    const float nx2 = __fmul_rn(__fdiv_rn(r.z, 1024.0f), (float)WW);
    const float ny2 = __fmul_rn(__fdiv_rn(r.w,  800.0f), (float)HH);

    int x1 = max((int)floorf(nx1), 0);
    int y1 = max((int)floorf(ny1), 0);
    int x2 = max((int)ceilf(nx2), 0);
    int y2 = max((int)ceilf(ny2), 0);

    if (x1 == 0 && x2 == 0) x2 = 1;
    if (y1 == 0 && y2 == 0) y2 = 1;
    if (x1 >= WW) x1 = WW - 1;
    if (y1 >= HH) y1 = HH - 1;

    const int xe = min(x2, WW);
    const int ye = min(y2, HH);

    const float* base = feat + ((size_t)(b * CC + c)) * HWSZ;
    const int x = x1 + xoff;
    const bool xok = (x < xe);

    float m = -INFINITY;

    // Window height <= 7 for this dataset: 8 predicated independent loads.
    #pragma unroll
    for (int j = 0; j < 8; ++j) {
        const int y = y1 + j;
        if (xok && y < ye)
            m = fmaxf(m, __ldg(base + y * WW + x));
    }
    // Safety tails (never taken with these shapes)
    for (int y = y1 + 8; y < ye; ++y)
        if (xok) m = fmaxf(m, __ldg(base + y * WW + x));
    for (int xx = x1 + 8; xx < xe; ++xx)
        for (int y = y1; y < ye; ++y)
            m = fmaxf(m, __ldg(base + y * WW + xx));

    // Reduce across the 8 window-column lanes (xor 1,2,4 stays in-group).
    m = fmaxf(m, __shfl_xor_sync(0xFFFFFFFFu, m, 1));
    m = fmaxf(m, __shfl_xor_sync(0xFFFFFFFFu, m, 2));
    m = fmaxf(m, __shfl_xor_sync(0xFFFFFFFFu, m, 4));

    if (xoff == 0)
        out[(size_t)bn * CC + c] = m;   // 4 lanes/warp -> 16B contiguous
}

extern "C" void kernel_launch(void* const* d_in, const int* in_sizes, int n_in,
                              void* d_out, int out_size)
{
    const float* feat = (const float*)d_in[0];   // [B, C, H, W]
    const float* rois = (const float*)d_in[1];   // [B, N, 4]
    float* out        = (float*)d_out;           // [B, N, C]
    (void)in_sizes; (void)n_in; (void)out_size;

    dim3 grid(BB * NN, CC / 32);                 // 256 x 16
    roipool_fused_kernel<<<grid, 256>>>(feat, rois, out);
}

// round 6
// speedup vs baseline: 1.1940x; 1.0209x over previous
#include <cuda_runtime.h>
#include <math.h>

// Shapes (fixed by dataset):
//   features: [B=2, C=512, H=50, W=64] float32
//   roiss   : [B=2, N=128, 4]          float32
//   out     : [B, N, C]                float32
#define BB 2
#define CC 512
#define HH 50
#define WW 64
#define NN 128
#define HWSZ (HH * WW)   // 3200

// ---------------------------------------------------------------------------
// Fused ROI max-pool, original [B, C, H, W] layout, float4 window loads.
//   grid  = (B*N, 8)  — blockIdx.x = roi, blockIdx.y = 64-channel tile
//   block = 256       — 8 warps; each warp: 8 channels x 4 float4 chunks
// Box computed ONCE per block (thread 0 -> smem). Window rows (<=7) are 8
// y-predicated LDG.128 per thread; column validity is applied ONCE at the
// end by masking float4 components to -inf, then 2x shfl_xor reduce.
// W=64 % 4 == 0, so an aligned chunk starting < W never crosses a row end.
// ---------------------------------------------------------------------------
struct Box { int x1, xe, y1, ye, xa; };

__global__ __launch_bounds__(256) void roipool_fused_kernel(
    const float* __restrict__ feat,
    const float* __restrict__ rois,
    float* __restrict__ out)
{
    const int bn    = blockIdx.x;           // 0 .. B*N-1
    const int b     = bn / NN;
    const int w     = threadIdx.x >> 5;     // warp 0..7
    const int lane  = threadIdx.x & 31;
    const int csub  = lane >> 2;            // 0..7  (channel within warp)
    const int chunk = lane & 3;             // 0..3  (float4 chunk)
    const int c     = blockIdx.y * 64 + w * 8 + csub;

    __shared__ Box sbox;

    if (threadIdx.x == 0) {
        // --- box computation (byte-identical to jax reference path) ---
        const float4 r = reinterpret_cast<const float4*>(rois)[bn];
        const float nx1 = __fmul_rn(__fdiv_rn(r.x, 1024.0f), (float)WW);
        const float ny1 = __fmul_rn(__fdiv_rn(r.y,  800.0f), (float)HH);
        const float nx2 = __fmul_rn(__fdiv_rn(r.z, 1024.0f), (float)WW);
        const float ny2 = __fmul_rn(__fdiv_rn(r.w,  800.0f), (float)HH);

        int x1 = max((int)floorf(nx1), 0);
        int y1 = max((int)floorf(ny1), 0);
        int x2 = max((int)ceilf(nx2), 0);
        int y2 = max((int)ceilf(ny2), 0);

        if (x1 == 0 && x2 == 0) x2 = 1;
        if (y1 == 0 && y2 == 0) y2 = 1;
        if (x1 >= WW) x1 = WW - 1;
        if (y1 >= HH) y1 = HH - 1;

        sbox.x1 = x1;
        sbox.xe = min(x2, WW);
        sbox.y1 = y1;
        sbox.ye = min(y2, HH);
        sbox.xa = x1 & ~3;                  // 16B-aligned window start
    }
    __syncthreads();

    const int x1 = sbox.x1, xe = sbox.xe, y1 = sbox.y1, ye = sbox.ye;
    const int xb = sbox.xa + chunk * 4;     // this thread's chunk start
    const bool chunk_ok = (xb < xe);        // chunk intersects window (right)

    const float* base = feat + ((size_t)(b * CC + c)) * HWSZ + xb;

    float4 m = make_float4(-INFINITY, -INFINITY, -INFINITY, -INFINITY);

    // Window height <= 7 for this dataset: 8 predicated LDG.128, independent.
    #pragma unroll
    for (int j = 0; j < 8; ++j) {
        const int y = y1 + j;
        if (chunk_ok && y < ye) {
            const float4 v = *reinterpret_cast<const float4*>(base + y * WW);
            m.x = fmaxf(m.x, v.x);
            m.y = fmaxf(m.y, v.y);
            m.z = fmaxf(m.z, v.z);
            m.w = fmaxf(m.w, v.w);
        }
    }
    // Safety tail for taller windows (never taken with these shapes)
    for (int y = y1 + 8; y < ye; ++y) {
        if (chunk_ok) {
            const float4 v = *reinterpret_cast<const float4*>(base + y * WW);
            m.x = fmaxf(m.x, v.x);
            m.y = fmaxf(m.y, v.y);
            m.z = fmaxf(m.z, v.z);
            m.w = fmaxf(m.w, v.w);
        }
    }
    // Safety tail for windows wider than 16 cols (never taken: width <= 7)
    for (int xx = sbox.xa + 16 + chunk; xx < xe; xx += 4)
        for (int y = y1; y < ye; ++y)
            m.x = fmaxf(m.x, __ldg(feat + ((size_t)(b * CC + c)) * HWSZ
                                        + y * WW + xx));

    // Apply column validity once: component k is x = xb + k.
    float v0 = (xb + 0 >= x1 && xb + 0 < xe) ? m.x : -INFINITY;
    float v1 = (xb + 1 >= x1 && xb + 1 < xe) ? m.y : -INFINITY;
    float v2 = (xb + 2 >= x1 && xb + 2 < xe) ? m.z : -INFINITY;
    float v3 = (xb + 3 >= x1 && xb + 3 < xe) ? m.w : -INFINITY;
    float v = fmaxf(fmaxf(v0, v1), fmaxf(v2, v3));

    // Reduce across the 4 chunk lanes (xor 1,2 stays within the group).
    v = fmaxf(v, __shfl_xor_sync(0xFFFFFFFFu, v, 1));
    v = fmaxf(v, __shfl_xor_sync(0xFFFFFFFFu, v, 2));

    if (chunk == 0)
        out[(size_t)bn * CC + c] = v;       // 8 lanes/warp -> 32B contiguous
}

extern "C" void kernel_launch(void* const* d_in, const int* in_sizes, int n_in,
                              void* d_out, int out_size)
{
    const float* feat = (const float*)d_in[0];   // [B, C, H, W]
    const float* rois = (const float*)d_in[1];   // [B, N, 4]
    float* out        = (float*)d_out;           // [B, N, C]
    (void)in_sizes; (void)n_in; (void)out_size;

    dim3 grid(BB * NN, CC / 64);                 // 256 x 8
    roipool_fused_kernel<<<grid, 256>>>(feat, rois, out);
}

// round 7
// speedup vs baseline: 1.4760x; 1.2362x over previous
#include <cuda_runtime.h>
#include <math.h>

// Shapes (fixed by dataset):
//   features: [B=2, C=512, H=50, W=64] float32
//   roiss   : [B=2, N=128, 4]          float32
//   out     : [B, N, C]                float32
#define BB 2
#define CC 512
#define HH 50
#define WW 64
#define NN 128
#define HWSZ (HH * WW)   // 3200

// ---------------------------------------------------------------------------
// Fused ROI max-pool, original [B, C, H, W] layout, float2 window loads.
//   grid  = (B*N, 8)  — blockIdx.x = roi, blockIdx.y = 64-channel tile
//   block = 256       — 8 warps; each warp: 8 channels x 4 float2 chunks
// Window width <= 7, so an 8-float span aligned to 2 (x1 & ~1) always covers
// it: 4 float2 chunks per channel. Box computed once per block. Rows (<=7)
// are 8 warp-uniform-predicated LDG.64 (MLP=8, no traffic when off). Column
// validity applied once at the end; 2x shfl_xor reduce across chunk lanes.
// ---------------------------------------------------------------------------
struct Box { int x1, xe, y1, ye, xa; };

__global__ __launch_bounds__(256, 8) void roipool_fused_kernel(
    const float* __restrict__ feat,
    const float* __restrict__ rois,
    float* __restrict__ out)
{
    const int bn    = blockIdx.x;           // 0 .. B*N-1
    const int b     = bn / NN;
    const int w     = threadIdx.x >> 5;     // warp 0..7
    const int lane  = threadIdx.x & 31;
    const int csub  = lane >> 2;            // 0..7  channel within warp
    const int chunk = lane & 3;             // 0..3  float2 chunk
    const int c     = blockIdx.y * 64 + w * 8 + csub;

    __shared__ Box sbox;

    if (threadIdx.x == 0) {
        // --- box computation (byte-identical to jax reference path) ---
        const float4 r = reinterpret_cast<const float4*>(rois)[bn];
        const float nx1 = __fmul_rn(__fdiv_rn(r.x, 1024.0f), (float)WW);
        const float ny1 = __fmul_rn(__fdiv_rn(r.y,  800.0f), (float)HH);
        const float nx2 = __fmul_rn(__fdiv_rn(r.z, 1024.0f), (float)WW);
        const float ny2 = __fmul_rn(__fdiv_rn(r.w,  800.0f), (float)HH);

        int x1 = max((int)floorf(nx1), 0);
        int y1 = max((int)floorf(ny1), 0);
        int x2 = max((int)ceilf(nx2), 0);
        int y2 = max((int)ceilf(ny2), 0);

        if (x1 == 0 && x2 == 0) x2 = 1;
        if (y1 == 0 && y2 == 0) y2 = 1;
        if (x1 >= WW) x1 = WW - 1;
        if (y1 >= HH) y1 = HH - 1;

        sbox.x1 = x1;
        sbox.xe = min(x2, WW);
        sbox.y1 = y1;
        sbox.ye = min(y2, HH);
        sbox.xa = x1 & ~1;                  // 8B-aligned window start
    }
    __syncthreads();

    const int x1 = sbox.x1, xe = sbox.xe, y1 = sbox.y1, ye = sbox.ye;
    const int xb = sbox.xa + chunk * 2;     // this thread's chunk start
    const bool chunk_ok = (xb < xe);        // keeps loads in-bounds too

    const float* base = feat + ((size_t)(b * CC + c)) * HWSZ + xb;

    float m0 = -INFINITY, m1 = -INFINITY;

    // Window height <= 7: 8 warp-uniform-predicated LDG.64, all independent.
    #pragma unroll
    for (int j = 0; j < 8; ++j) {
        const int y = y1 + j;
        if (chunk_ok && y < ye) {
            const float2 v = *reinterpret_cast<const float2*>(base + y * WW);
            m0 = fmaxf(m0, v.x);
            m1 = fmaxf(m1, v.y);
        }
    }
    // Safety tail for taller windows (never taken with these shapes)
    for (int y = y1 + 8; y < ye; ++y) {
        if (chunk_ok) {
            const float2 v = *reinterpret_cast<const float2*>(base + y * WW);
            m0 = fmaxf(m0, v.x);
            m1 = fmaxf(m1, v.y);
        }
    }
    // Safety tail for windows wider than the 8-float span (never taken)
    for (int xx = sbox.xa + 8 + chunk; xx < xe; xx += 4)
        for (int y = y1; y < ye; ++y)
            m0 = fmaxf(m0, __ldg(feat + ((size_t)(b * CC + c)) * HWSZ
                                      + y * WW + xx));

    // Apply column validity once: component k is x = xb + k.
    const float v0 = (xb + 0 >= x1 && xb + 0 < xe) ? m0 : -INFINITY;
    const float v1 = (xb + 1 >= x1 && xb + 1 < xe) ? m1 : -INFINITY;
    float v = fmaxf(v0, v1);

    // Reduce across the 4 chunk lanes (xor 1,2 stays within the group).
    v = fmaxf(v, __shfl_xor_sync(0xFFFFFFFFu, v, 1));
    v = fmaxf(v, __shfl_xor_sync(0xFFFFFFFFu, v, 2));

    if (chunk == 0)
        out[(size_t)bn * CC + c] = v;       // 8 lanes/warp -> 32B contiguous
}

extern "C" void kernel_launch(void* const* d_in, const int* in_sizes, int n_in,
                              void* d_out, int out_size)
{
    const float* feat = (const float*)d_in[0];   // [B, C, H, W]
    const float* rois = (const float*)d_in[1];   // [B, N, 4]
    float* out        = (float*)d_out;           // [B, N, C]
    (void)in_sizes; (void)n_in; (void)out_size;

    dim3 grid(BB * NN, CC / 64);                 // 256 x 8
    roipool_fused_kernel<<<grid, 256>>>(feat, rois, out);
}